// round 4
// baseline (speedup 1.0000x reference)
#include <cuda_runtime.h>
#include <cuda_bf16.h>
#include <cstdint>

#define NN 12288
#define EE 196608
#define FIN 1433
#define KP 1440            // 90 * 16, zero-padded W
#define NSTEP 90
#define H1 32
#define H2 16
#define NC 7

// ---------------- scratch ----------------
__device__ __align__(16) float g_y[NN * H1];
__device__ __align__(16) float g_acc[NN * H1];
__device__ __align__(16) float g_h[NN * H1];
__device__ __align__(16) float g_sg[NN * H1];
__device__ int   g_deg[NN];
__device__ int   g_cnt[NN];
__device__ __align__(16) __nv_bfloat16 g_wh[H1 * KP];  // W1^T hi  [n][k]
__device__ __align__(16) __nv_bfloat16 g_wl[H1 * KP];  // W1^T lo  [n][k]

// ---------------- helpers ----------------
__device__ __forceinline__ void red4(float* p, float4 v) {
    asm volatile("red.global.add.v4.f32 [%0], {%1,%2,%3,%4};"
                 :: "l"(p), "f"(v.x), "f"(v.y), "f"(v.z), "f"(v.w) : "memory");
}

__device__ __forceinline__ void mma_bf16(float* c, const uint32_t* a,
                                         uint32_t b0, uint32_t b1) {
    asm volatile(
        "mma.sync.aligned.m16n8k16.row.col.f32.bf16.bf16.f32 "
        "{%0,%1,%2,%3}, {%4,%5,%6,%7}, {%8,%9}, {%0,%1,%2,%3};"
        : "+f"(c[0]), "+f"(c[1]), "+f"(c[2]), "+f"(c[3])
        : "r"(a[0]), "r"(a[1]), "r"(a[2]), "r"(a[3]), "r"(b0), "r"(b1));
}

// per-block int64-vs-int32 edge dtype detection
__device__ __forceinline__ int detect64(const void* ei, int* s_flag) {
    if (threadIdx.x < 32) {
        int ok = (((const int*)ei)[2 * threadIdx.x + 1] == 0);
        int all = __all_sync(0xffffffffu, ok);
        if (threadIdx.x == 0) *s_flag = all;
    }
    __syncthreads();
    return *s_flag;
}
__device__ __forceinline__ int eload(const void* ei, int is64, int which, int e) {
    if (is64) return (int)(((const long long*)ei)[(long long)which * EE + e]);
    return ((const int*)ei)[which * EE + e];
}

// ---------------- prep: W split + init ----------------
__global__ void k_prep(const float* __restrict__ W1) {
    int idx = blockIdx.x * blockDim.x + threadIdx.x;
    if (idx < H1 * KP) {
        int n = idx / KP, k = idx % KP;
        float w = (k < FIN) ? W1[k * H1 + n] : 0.f;
        __nv_bfloat16 hb = __float2bfloat16_rn(w);
        float lo = w - __bfloat162float(hb);
        g_wh[idx] = hb;
        g_wl[idx] = __float2bfloat16_rn(lo);
    }
    if (idx < NN) { g_deg[idx] = 1; g_cnt[idx] = 0; }
    if (idx < NN * H1) { g_acc[idx] = 0.f; g_sg[idx] = 0.f; }
}

// ---------------- degree / out-count ----------------
__global__ void k_count(const void* ei) {
    __shared__ int s64;
    int is64 = detect64(ei, &s64);
    int e = blockIdx.x * blockDim.x + threadIdx.x;
    if (e < EE) {
        atomicAdd(&g_deg[eload(ei, is64, 1, e)], 1);
        atomicAdd(&g_cnt[eload(ei, is64, 0, e)], 1);
    }
}

// ---------------- HMMA GEMM: y = x @ W1 (bf16 3-term split, no smem) ----------------
// 256 thr = 8 warps; warp handles 16 rows x 32 cols; full K per CTA; grid 96.
__device__ __forceinline__ void ldx8(const float* __restrict__ xr0,
                                     const float* __restrict__ xr1,
                                     int c0, float* f) {
    const bool m0 = (c0     < FIN), m1 = (c0 + 1 < FIN);
    const bool m8 = (c0 + 8 < FIN), m9 = (c0 + 9 < FIN);
    f[0] = m0 ? __ldg(xr0 + c0)     : 0.f;
    f[1] = m1 ? __ldg(xr0 + c0 + 1) : 0.f;
    f[2] = m0 ? __ldg(xr1 + c0)     : 0.f;
    f[3] = m1 ? __ldg(xr1 + c0 + 1) : 0.f;
    f[4] = m8 ? __ldg(xr0 + c0 + 8) : 0.f;
    f[5] = m9 ? __ldg(xr0 + c0 + 9) : 0.f;
    f[6] = m8 ? __ldg(xr1 + c0 + 8) : 0.f;
    f[7] = m9 ? __ldg(xr1 + c0 + 9) : 0.f;
}

__device__ __forceinline__ void split2(float c0, float c1, uint32_t& hi, uint32_t& lo) {
    __nv_bfloat162 hb = __floats2bfloat162_rn(c0, c1);
    float l0 = c0 - __bfloat162float(hb.x);
    float l1 = c1 - __bfloat162float(hb.y);
    __nv_bfloat162 lb = __floats2bfloat162_rn(l0, l1);
    hi = *(uint32_t*)&hb;
    lo = *(uint32_t*)&lb;
}

__global__ void __launch_bounds__(256) k_gemm(const float* __restrict__ x) {
    const int tid = threadIdx.x, wid = tid >> 5, lane = tid & 31;
    const int gid = lane >> 2;
    const int t2  = (lane & 3) * 2;
    const int r0  = blockIdx.x * 128 + wid * 16 + gid;
    const int r1  = r0 + 8;
    const float* xr0 = x + (long long)r0 * FIN;
    const float* xr1 = x + (long long)r1 * FIN;

    float acc[4][4];
    #pragma unroll
    for (int nb = 0; nb < 4; nb++)
        #pragma unroll
        for (int q = 0; q < 4; q++) acc[nb][q] = 0.f;

    float cur[8], nxt[8];
    ldx8(xr0, xr1, t2, cur);

    for (int s = 0; s < NSTEP; s++) {
        const int k0 = s * 16;
        if (s + 1 < NSTEP) ldx8(xr0, xr1, (s + 1) * 16 + t2, nxt);

        uint32_t ah[4], al[4];
        split2(cur[0], cur[1], ah[0], al[0]);
        split2(cur[2], cur[3], ah[1], al[1]);
        split2(cur[4], cur[5], ah[2], al[2]);
        split2(cur[6], cur[7], ah[3], al[3]);

        #pragma unroll
        for (int nb = 0; nb < 4; nb++) {
            const int n = nb * 8 + gid;
            const uint32_t bh0 = *(const uint32_t*)&g_wh[n * KP + k0 + t2];
            const uint32_t bh1 = *(const uint32_t*)&g_wh[n * KP + k0 + 8 + t2];
            const uint32_t bl0 = *(const uint32_t*)&g_wl[n * KP + k0 + t2];
            const uint32_t bl1 = *(const uint32_t*)&g_wl[n * KP + k0 + 8 + t2];
            mma_bf16(acc[nb], ah, bh0, bh1);
            mma_bf16(acc[nb], al, bh0, bh1);
            mma_bf16(acc[nb], ah, bl0, bl1);
        }
        #pragma unroll
        for (int q = 0; q < 8; q++) cur[q] = nxt[q];
    }

    #pragma unroll
    for (int nb = 0; nb < 4; nb++) {
        float2 v0 = make_float2(acc[nb][0], acc[nb][1]);
        float2 v1 = make_float2(acc[nb][2], acc[nb][3]);
        *(float2*)&g_y[r0 * H1 + nb * 8 + t2] = v0;
        *(float2*)&g_y[r1 * H1 + nb * 8 + t2] = v1;
    }
}

// ---------------- GCN edge aggregation (v4 red) ----------------
__global__ void k_gcn(const void* ei) {
    __shared__ int s64;
    int is64 = detect64(ei, &s64);
    int idx = blockIdx.x * blockDim.x + threadIdx.x;   // EE*8 threads
    int e = idx >> 3, g = idx & 7;
    int r  = eload(ei, is64, 0, e);
    int cl = eload(ei, is64, 1, e);
    float s = rsqrtf((float)g_deg[cl]);
    float4 v = *(const float4*)&g_y[cl * H1 + g * 4];
    v.x *= s; v.y *= s; v.z *= s; v.w *= s;
    red4(&g_acc[r * H1 + g * 4], v);
}

// ---------------- h = relu(dis*(acc + dis*y) + b1) ----------------
__global__ void k_h(const float* __restrict__ b1) {
    int idx = blockIdx.x * blockDim.x + threadIdx.x;   // NN*8
    int i = idx >> 3, g = idx & 7;
    float d = rsqrtf((float)g_deg[i]);
    float4 a = *(const float4*)&g_acc[idx * 4];
    float4 y = *(const float4*)&g_y[idx * 4];
    float4 b = *(const float4*)&b1[g * 4];
    float4 o;
    o.x = fmaxf(d * (a.x + d * y.x) + b.x, 0.f);
    o.y = fmaxf(d * (a.y + d * y.y) + b.y, 0.f);
    o.z = fmaxf(d * (a.z + d * y.z) + b.z, 0.f);
    o.w = fmaxf(d * (a.w + d * y.w) + b.w, 0.f);
    *(float4*)&g_h[idx * 4] = o;
}

// ---------------- SAGE aggregation (v4 red) ----------------
__global__ void k_sage(const void* ei) {
    __shared__ int s64;
    int is64 = detect64(ei, &s64);
    int idx = blockIdx.x * blockDim.x + threadIdx.x;
    int e = idx >> 3, g = idx & 7;
    int s = eload(ei, is64, 0, e);
    int d = eload(ei, is64, 1, e);
    float4 v = *(const float4*)&g_h[d * H1 + g * 4];
    red4(&g_sg[s * H1 + g * 4], v);
}

// ---------------- head ----------------
__global__ void __launch_bounds__(256) k_head(const float* __restrict__ Wl,
                                              const float* __restrict__ bl,
                                              const float* __restrict__ Wr,
                                              const float* __restrict__ br,
                                              const float* __restrict__ W3,
                                              const float* __restrict__ b3,
                                              float* __restrict__ out) {
    __shared__ float sWl[H1 * H2], sWr[H1 * H2], sW3[H2 * NC];
    __shared__ float sbl[H2], sbr[H2], sb3[NC];
    const int tid = threadIdx.x;
    for (int i = tid; i < H1 * H2; i += blockDim.x) { sWl[i] = Wl[i]; sWr[i] = Wr[i]; }
    for (int i = tid; i < H2 * NC; i += blockDim.x) sW3[i] = W3[i];
    if (tid < H2) { sbl[tid] = bl[tid]; sbr[tid] = br[tid]; }
    if (tid < NC) sb3[tid] = b3[tid];
    __syncthreads();

    const int n = blockIdx.x * blockDim.x + tid;
    if (n >= NN) return;
    const float invc = 1.0f / fmaxf((float)g_cnt[n], 1.0f);

    float t[H2];
    #pragma unroll
    for (int j = 0; j < H2; j++) t[j] = sbl[j] + sbr[j];
    #pragma unroll 4
    for (int c = 0; c < H1; c++) {
        const float hv = g_h[n * H1 + c];
        const float av = g_sg[n * H1 + c] * invc;
        #pragma unroll
        for (int j = 0; j < H2; j++)
            t[j] += hv * sWl[c * H2 + j] + av * sWr[c * H2 + j];
    }
    float ss = 0.f;
    #pragma unroll
    for (int j = 0; j < H2; j++) { t[j] = fmaxf(t[j], 0.f); ss += t[j] * t[j]; }
    const float sc = 1.0f / (sqrtf(ss) + 1e-6f);

    float lg[NC];
    #pragma unroll
    for (int k = 0; k < NC; k++) lg[k] = sb3[k];
    #pragma unroll
    for (int j = 0; j < H2; j++) {
        const float tv = t[j] * sc;
        #pragma unroll
        for (int k = 0; k < NC; k++) lg[k] += tv * sW3[j * NC + k];
    }
    float mx = lg[0];
    #pragma unroll
    for (int k = 1; k < NC; k++) mx = fmaxf(mx, lg[k]);
    float se = 0.f;
    #pragma unroll
    for (int k = 0; k < NC; k++) { lg[k] = __expf(lg[k] - mx); se += lg[k]; }
    const float inv = 1.0f / se;
    #pragma unroll
    for (int k = 0; k < NC; k++) out[n * NC + k] = lg[k] * inv;
}

extern "C" void kernel_launch(void* const* d_in, const int* in_sizes, int n_in,
                              void* d_out, int out_size) {
    const float* x  = (const float*)d_in[0];
    const void*  ei = d_in[1];
    const float* W1 = (const float*)d_in[2];
    const float* b1 = (const float*)d_in[3];
    const float* Wl = (const float*)d_in[4];
    const float* bl = (const float*)d_in[5];
    const float* Wr = (const float*)d_in[6];
    const float* br = (const float*)d_in[7];
    const float* W3 = (const float*)d_in[8];
    const float* b3 = (const float*)d_in[9];
    float* out = (float*)d_out;

    k_prep<<<(NN * H1 + 255) / 256, 256>>>(W1);
    k_count<<<EE / 256, 256>>>(ei);
    k_gemm<<<NN / 128, 256>>>(x);
    k_gcn<<<(EE * 8) / 256, 256>>>(ei);
    k_h<<<(NN * 8) / 256, 256>>>(b1);
    k_sage<<<(EE * 8) / 256, 256>>>(ei);
    k_head<<<(NN + 255) / 256, 256>>>(Wl, bl, Wr, br, W3, b3, out);
}